// round 5
// baseline (speedup 1.0000x reference)
#include <cuda_runtime.h>
#include <math.h>

#define N_NODES 50000
#define N_EDGES 640000
// dims: 128 -> 256 -> 128

// ---------------- scratch (allocation-free: __device__ globals) ----------------
// RULE: these are ONLY referenced inside __global__/__device__ code, never
// passed as kernel arguments from host (host-side shadow symbol + GB300 ATS
// silently redirects accesses to host RAM).
__device__ float4 g_agg1[N_NODES * 32];   // 50000 x 128 f32
__device__ float4 g_y1  [N_NODES * 64];   // 50000 x 256 f32
__device__ float4 g_agg2[N_NODES * 64];   // 50000 x 256 f32
__device__ int    g_deg [N_NODES];
__device__ float  g_invd[N_NODES];
__device__ int    g_idx64;                // 1 if edge_index is int64 in memory

// ---------------- edge index accessor (handles int32 or int64 storage) ----------------
__device__ __forceinline__ int edge_at(const int* __restrict__ ei, int which, int e) {
    if (g_idx64) return ei[((size_t)which * N_EDGES + (size_t)e) * 2];
    return ei[which * N_EDGES + e];
}

__global__ void k_detect(const int* __restrict__ ei) {
    if (blockIdx.x == 0 && threadIdx.x == 0) {
        int orr = 0;
#pragma unroll
        for (int i = 0; i < 16; i++) orr |= ei[2 * i + 1];
        g_idx64 = (orr == 0) ? 1 : 0;
    }
}

// ---------------- init: agg1 = x, deg = 1 ----------------
__global__ void k_init(const float4* __restrict__ x) {
    int i = blockIdx.x * blockDim.x + threadIdx.x;
    int stride = gridDim.x * blockDim.x;
    for (int j = i; j < N_NODES * 32; j += stride) g_agg1[j] = x[j];
    for (int j = i; j < N_NODES; j += stride) g_deg[j] = 1;
}

__global__ void k_deg_edges(const int* __restrict__ ei) {
    int e = blockIdx.x * blockDim.x + threadIdx.x;
    if (e < N_EDGES) atomicAdd(&g_deg[edge_at(ei, 1, e)], 1);
}

__global__ void k_invdeg() {
    int i = blockIdx.x * blockDim.x + threadIdx.x;
    if (i < N_NODES) g_invd[i] = 1.0f / (float)g_deg[i];
}

__global__ void k_copy_y1() {
    int i = blockIdx.x * blockDim.x + threadIdx.x;
    if (i < N_NODES * 64) g_agg2[i] = g_y1[i];
}

// ---------------- scatter layer 1: g_agg1[dst] += x[src], one warp per edge ----------------
__global__ void k_scat1(const int* __restrict__ ei, const float4* __restrict__ x) {
    int gt = blockIdx.x * blockDim.x + threadIdx.x;
    int e = gt >> 5;
    int lane = gt & 31;
    if (e >= N_EDGES) return;
    int s = edge_at(ei, 0, e);
    int d = edge_at(ei, 1, e);
    float4 v = __ldg(&x[(size_t)s * 32 + lane]);
    float* p = ((float*)g_agg1) + (size_t)d * 128 + lane * 4;
    atomicAdd(p + 0, v.x);
    atomicAdd(p + 1, v.y);
    atomicAdd(p + 2, v.z);
    atomicAdd(p + 3, v.w);
}

// ---------------- scatter layer 2: g_agg2[dst] += g_y1[src] ----------------
__global__ void k_scat2(const int* __restrict__ ei) {
    int gt = blockIdx.x * blockDim.x + threadIdx.x;
    int e = gt >> 5;
    int lane = gt & 31;
    if (e >= N_EDGES) return;
    int s = edge_at(ei, 0, e);
    int d = edge_at(ei, 1, e);
#pragma unroll
    for (int j = 0; j < 2; j++) {
        float4 v = g_y1[(size_t)s * 64 + lane + 32 * j];
        float* p = ((float*)g_agg2) + (size_t)d * 256 + (lane + 32 * j) * 4;
        atomicAdd(p + 0, v.x);
        atomicAdd(p + 1, v.y);
        atomicAdd(p + 2, v.z);
        atomicAdd(p + 3, v.w);
    }
}

// ---------------- lin1: y1 = relu((agg1*invd) @ W1^T + b1), K=128, NOUT=256 ----------------
#define NGROUPS 3125            // 50000 / 16 exactly
#define SMEM_LIN1 ((256 * 33 + 16 * 32) * 16)
__global__ void __launch_bounds__(256, 1)
k_lin1(const float4* __restrict__ W1, const float* __restrict__ b1) {
    extern __shared__ float4 smem4[];
    float4* Wsh = smem4;               // [256][33]
    float4* Ash = smem4 + 256 * 33;    // [16][32]
    int t = threadIdx.x;

    for (int i = t; i < 256 * 32; i += 256)
        Wsh[(i >> 5) * 33 + (i & 31)] = __ldg(&W1[i]);
    float bias = __ldg(&b1[t]);

    for (int g = blockIdx.x; g < NGROUPS; g += gridDim.x) {
        int base = g * 16;
        __syncthreads();
        for (int i = t; i < 16 * 32; i += 256) {
            int r = i >> 5, k = i & 31;
            int row = base + r;
            float4 v = g_agg1[(size_t)row * 32 + k];
            float s = g_invd[row];
            v.x *= s; v.y *= s; v.z *= s; v.w *= s;
            Ash[r * 32 + k] = v;
        }
        __syncthreads();

        float acc[16];
#pragma unroll
        for (int r = 0; r < 16; r++) acc[r] = 0.f;
#pragma unroll 4
        for (int k4 = 0; k4 < 32; k4++) {
            float4 w = Wsh[t * 33 + k4];
#pragma unroll
            for (int r = 0; r < 16; r++) {
                float4 a = Ash[r * 32 + k4];
                acc[r] += a.x * w.x + a.y * w.y + a.z * w.z + a.w * w.w;
            }
        }
        float* Y = (float*)g_y1;
#pragma unroll
        for (int r = 0; r < 16; r++)
            Y[(size_t)(base + r) * 256 + t] = fmaxf(acc[r] + bias, 0.f);
    }
}

// ---------------- lin2: out = normalize((agg2*invd) @ W2^T + b2) * exp(ls), K=256, NOUT=128
#define SMEM_LIN2 ((128 * 65 + 16 * 64) * 16 + 16 * 4 * 4)
__global__ void __launch_bounds__(128, 1)
k_lin2(const float4* __restrict__ W2, const float* __restrict__ b2,
       const float* __restrict__ logit, float* __restrict__ out) {
    extern __shared__ float4 smem4[];
    float4* Wsh = smem4;               // [128][65]
    float4* Ash = smem4 + 128 * 65;    // [16][64]
    float*  red = (float*)(Ash + 16 * 64);   // [16][4]
    int t = threadIdx.x;
    int lane = t & 31, wid = t >> 5;

    for (int i = t; i < 128 * 64; i += 128)
        Wsh[(i >> 6) * 65 + (i & 63)] = __ldg(&W2[i]);
    float bias = __ldg(&b2[t]);
    float sc = expf(__ldg(logit));

    for (int g = blockIdx.x; g < NGROUPS; g += gridDim.x) {
        int base = g * 16;
        __syncthreads();
        for (int i = t; i < 16 * 64; i += 128) {
            int r = i >> 6, k = i & 63;
            int row = base + r;
            float4 v = g_agg2[(size_t)row * 64 + k];
            float s = g_invd[row];
            v.x *= s; v.y *= s; v.z *= s; v.w *= s;
            Ash[r * 64 + k] = v;
        }
        __syncthreads();

        float acc[16];
#pragma unroll
        for (int r = 0; r < 16; r++) acc[r] = 0.f;
#pragma unroll 4
        for (int k4 = 0; k4 < 64; k4++) {
            float4 w = Wsh[t * 65 + k4];
#pragma unroll
            for (int r = 0; r < 16; r++) {
                float4 a = Ash[r * 64 + k4];
                acc[r] += a.x * w.x + a.y * w.y + a.z * w.z + a.w * w.w;
            }
        }
#pragma unroll
        for (int r = 0; r < 16; r++) {
            acc[r] += bias;
            float ss = acc[r] * acc[r];
#pragma unroll
            for (int off = 16; off > 0; off >>= 1)
                ss += __shfl_xor_sync(0xffffffffu, ss, off);
            if (lane == 0) red[r * 4 + wid] = ss;
        }
        __syncthreads();
#pragma unroll
        for (int r = 0; r < 16; r++) {
            float tot = red[r * 4 + 0] + red[r * 4 + 1] + red[r * 4 + 2] + red[r * 4 + 3];
            float sca = sc / fmaxf(sqrtf(tot), 1e-12f);
            out[(size_t)(base + r) * 128 + t] = acc[r] * sca;
        }
    }
}

// ---------------- launch ----------------
extern "C" void kernel_launch(void* const* d_in, const int* in_sizes, int n_in,
                              void* d_out, int out_size) {
    // resolve inputs by element count (robust to ordering); W1 before W2 in metadata order
    const void *px = 0, *pei = 0, *pW1 = 0, *pb1 = 0, *pW2 = 0, *pb2 = 0, *pls = 0;
    int nW = 0;
    for (int i = 0; i < n_in; i++) {
        switch (in_sizes[i]) {
            case 6400000: px = d_in[i]; break;
            case 1280000: pei = d_in[i]; break;
            case 32768:   if (nW++ == 0) pW1 = d_in[i]; else pW2 = d_in[i]; break;
            case 256:     pb1 = d_in[i]; break;
            case 128:     pb2 = d_in[i]; break;
            case 1:       pls = d_in[i]; break;
            default: break;
        }
    }
    if (!px)  px  = d_in[0];
    if (!pei) pei = d_in[1];
    if (!pW1) pW1 = d_in[2];
    if (!pb1) pb1 = d_in[3];
    if (!pW2) pW2 = d_in[4];
    if (!pb2) pb2 = d_in[5];
    if (!pls) pls = d_in[6];

    const float4* x  = (const float4*)px;
    const int*    ei = (const int*)pei;
    const float4* W1 = (const float4*)pW1;
    const float*  b1 = (const float*)pb1;
    const float4* W2 = (const float4*)pW2;
    const float*  b2 = (const float*)pb2;
    const float*  ls = (const float*)pls;
    float*        out = (float*)d_out;

    cudaFuncSetAttribute(k_lin1, cudaFuncAttributeMaxDynamicSharedMemorySize, SMEM_LIN1);
    cudaFuncSetAttribute(k_lin2, cudaFuncAttributeMaxDynamicSharedMemorySize, SMEM_LIN2);

    int scatter_blocks = (N_EDGES * 32 + 255) / 256;   // one warp per edge

    k_detect<<<1, 32>>>(ei);
    k_init<<<2048, 256>>>(x);
    k_deg_edges<<<(N_EDGES + 255) / 256, 256>>>(ei);
    k_invdeg<<<(N_NODES + 255) / 256, 256>>>();
    k_scat1<<<scatter_blocks, 256>>>(ei, x);
    k_lin1<<<304, 256, SMEM_LIN1>>>(W1, b1);
    k_copy_y1<<<12500, 256>>>();
    k_scat2<<<scatter_blocks, 256>>>(ei);
    k_lin2<<<304, 128, SMEM_LIN2>>>(W2, b2, ls, out);
}

// round 6
// speedup vs baseline: 2.8786x; 2.8786x over previous
#include <cuda_runtime.h>
#include <math.h>

#define N_NODES 50000
#define N_EDGES 640000
// dims: 128 -> 256 -> 128

// ---------------- scratch (device-code-only references; never host args) ----------------
__device__ float4 g_agg1[N_NODES * 32];   // 50000 x 128 (x self + neighbor sum)
__device__ float4 g_y1  [N_NODES * 64];   // 50000 x 256 relu(lin1)
__device__ float4 g_z   [N_NODES * 32];   // 50000 x 128 (y1 @ W2^T, pre-aggregation)
__device__ float4 g_agg2[N_NODES * 32];   // 50000 x 128 (z self + neighbor sum)
__device__ int    g_dege[N_NODES];        // edge-only degree
__device__ float  g_invd[N_NODES];        // 1/(dege+1)
__device__ int    g_rowstart[N_NODES + 1];
__device__ int    g_cursor[N_NODES];
__device__ int    g_csr[N_EDGES];         // src indices grouped by dst
__device__ int    g_idx64;

// ---------------- edge index accessor (int32 or int64 storage) ----------------
__device__ __forceinline__ int edge_at(const int* __restrict__ ei, int which, int e) {
    if (g_idx64) return ei[((size_t)which * N_EDGES + (size_t)e) * 2];
    return ei[which * N_EDGES + e];
}

__global__ void k_detect(const int* __restrict__ ei) {
    if (threadIdx.x == 0) {
        int orr = 0;
#pragma unroll
        for (int i = 0; i < 16; i++) orr |= ei[2 * i + 1];
        g_idx64 = (orr == 0) ? 1 : 0;
    }
}

__global__ void k_zero() {
    int i = blockIdx.x * blockDim.x + threadIdx.x;
    if (i < N_NODES) { g_dege[i] = 0; g_cursor[i] = 0; }
}

__global__ void k_deg(const int* __restrict__ ei) {
    int e = blockIdx.x * blockDim.x + threadIdx.x;
    if (e < N_EDGES) atomicAdd(&g_dege[edge_at(ei, 1, e)], 1);
}

__global__ void k_invdeg() {
    int i = blockIdx.x * blockDim.x + threadIdx.x;
    if (i < N_NODES) g_invd[i] = 1.0f / (float)(g_dege[i] + 1);
}

// ---------------- exclusive scan of g_dege -> g_rowstart (single block, 1024 thr) ----------------
__global__ void __launch_bounds__(1024, 1) k_scan() {
    __shared__ int wsum[32];
    __shared__ int s_carry;
    int t = threadIdx.x, lane = t & 31, w = t >> 5;
    if (t == 0) { s_carry = 0; g_rowstart[N_NODES] = N_EDGES; }
    __syncthreads();
    for (int base = 0; base < N_NODES; base += 1024) {
        int i = base + t;
        int v = (i < N_NODES) ? g_dege[i] : 0;
        int x = v;
#pragma unroll
        for (int off = 1; off < 32; off <<= 1) {
            int y = __shfl_up_sync(0xffffffffu, x, off);
            if (lane >= off) x += y;
        }
        if (lane == 31) wsum[w] = x;
        __syncthreads();
        if (t < 32) {
            int s = wsum[t];
#pragma unroll
            for (int off = 1; off < 32; off <<= 1) {
                int y = __shfl_up_sync(0xffffffffu, s, off);
                if (t >= off) s += y;
            }
            wsum[t] = s;
        }
        __syncthreads();
        int incl = x + (w > 0 ? wsum[w - 1] : 0);
        int carry = s_carry;
        if (i < N_NODES) g_rowstart[i] = carry + incl - v;
        int total = wsum[31];
        __syncthreads();
        if (t == 0) s_carry = carry + total;
        __syncthreads();
    }
}

__global__ void k_fill(const int* __restrict__ ei) {
    int e = blockIdx.x * blockDim.x + threadIdx.x;
    if (e >= N_EDGES) return;
    int s = edge_at(ei, 0, e);
    int d = edge_at(ei, 1, e);
    int off = atomicAdd(&g_cursor[d], 1);
    g_csr[g_rowstart[d] + off] = s;
}

// ---------------- gather1: agg1[d] = x[d] + sum_{s in N(d)} x[s]  (128-dim) ----------------
__global__ void k_gather1(const float4* __restrict__ x) {
    int gt = blockIdx.x * blockDim.x + threadIdx.x;
    int d = gt >> 5, lane = gt & 31;
    if (d >= N_NODES) return;
    int s0 = g_rowstart[d], s1 = g_rowstart[d + 1];
    float4 acc = __ldg(&x[(size_t)d * 32 + lane]);
    for (int i = s0; i < s1; i += 32) {
        int lim = s1 - i;
#pragma unroll
        for (int j = 0; j < 32; j++) {
            if (j < lim) {
                int s = __ldg(&g_csr[i + j]);
                float4 v = __ldg(&x[(size_t)s * 32 + lane]);
                acc.x += v.x; acc.y += v.y; acc.z += v.z; acc.w += v.w;
            }
        }
    }
    g_agg1[(size_t)d * 32 + lane] = acc;
}

// ---------------- gather2: agg2[d] = z[d] + sum z[s]  (128-dim) ----------------
__global__ void k_gather2() {
    int gt = blockIdx.x * blockDim.x + threadIdx.x;
    int d = gt >> 5, lane = gt & 31;
    if (d >= N_NODES) return;
    int s0 = g_rowstart[d], s1 = g_rowstart[d + 1];
    float4 acc = g_z[(size_t)d * 32 + lane];
    for (int i = s0; i < s1; i += 32) {
        int lim = s1 - i;
#pragma unroll
        for (int j = 0; j < 32; j++) {
            if (j < lim) {
                int s = __ldg(&g_csr[i + j]);
                float4 v = g_z[(size_t)s * 32 + lane];
                acc.x += v.x; acc.y += v.y; acc.z += v.z; acc.w += v.w;
            }
        }
    }
    g_agg2[(size_t)d * 32 + lane] = acc;
}

// ---------------- lin1: y1 = relu((agg1*invd) @ W1^T + b1), 128 -> 256 ----------------
// Persistent CTAs. Tile: 128 rows x 256 cols, 512 threads, 16r x 4c per thread.
// W1 resident in smem for whole kernel. smem = (256*33 + 128*33)*16 = 198KB.
#define NTILES ((N_NODES + 127) / 128)   // 391
#define SMEM_LIN1 ((256 * 33 + 128 * 33) * 16)
__global__ void __launch_bounds__(512, 1)
k_lin1(const float4* __restrict__ W1, const float* __restrict__ b1) {
    extern __shared__ float4 smem4[];
    float4* Ws = smem4;               // [256][33]
    float4* As = smem4 + 256 * 33;    // [128][33]
    int t = threadIdx.x;
    int cg = t & 63, rg = t >> 6;     // cols {cg,+64,+128,+192}; rows rg*16..+15

    for (int i = t; i < 256 * 32; i += 512)
        Ws[(i >> 5) * 33 + (i & 31)] = __ldg(&W1[i]);
    float bb[4];
#pragma unroll
    for (int j = 0; j < 4; j++) bb[j] = __ldg(&b1[cg + 64 * j]);

    for (int tile = blockIdx.x; tile < NTILES; tile += gridDim.x) {
        int base = tile * 128;
        __syncthreads();
        for (int i = t; i < 128 * 32; i += 512) {
            int r = i >> 5, k = i & 31;
            int row = base + r;
            float4 v = make_float4(0.f, 0.f, 0.f, 0.f);
            if (row < N_NODES) {
                v = g_agg1[(size_t)row * 32 + k];
                float s = g_invd[row];
                v.x *= s; v.y *= s; v.z *= s; v.w *= s;
            }
            As[r * 33 + k] = v;
        }
        __syncthreads();

        float acc[16][4];
#pragma unroll
        for (int r = 0; r < 16; r++)
#pragma unroll
            for (int j = 0; j < 4; j++) acc[r][j] = 0.f;

#pragma unroll 2
        for (int k4 = 0; k4 < 32; k4++) {
            float4 w0 = Ws[(cg      ) * 33 + k4];
            float4 w1 = Ws[(cg +  64) * 33 + k4];
            float4 w2 = Ws[(cg + 128) * 33 + k4];
            float4 w3 = Ws[(cg + 192) * 33 + k4];
#pragma unroll
            for (int r = 0; r < 16; r++) {
                float4 a = As[(rg * 16 + r) * 33 + k4];
                acc[r][0] += a.x * w0.x + a.y * w0.y + a.z * w0.z + a.w * w0.w;
                acc[r][1] += a.x * w1.x + a.y * w1.y + a.z * w1.z + a.w * w1.w;
                acc[r][2] += a.x * w2.x + a.y * w2.y + a.z * w2.z + a.w * w2.w;
                acc[r][3] += a.x * w3.x + a.y * w3.y + a.z * w3.z + a.w * w3.w;
            }
        }

        float* Y = (float*)g_y1;
#pragma unroll
        for (int r = 0; r < 16; r++) {
            int row = base + rg * 16 + r;
            if (row < N_NODES) {
#pragma unroll
                for (int j = 0; j < 4; j++)
                    Y[(size_t)row * 256 + cg + 64 * j] = fmaxf(acc[r][j] + bb[j], 0.f);
            }
        }
    }
}

// ---------------- lin2a: z = y1 @ W2^T (no bias), 256 -> 128 ----------------
// Tile: 128 rows x 128 cols, 512 threads, 8r x 4c. K=256 in 2 chunks of 128.
#define SMEM_LIN2 ((128 * 33 + 128 * 33) * 16)
__global__ void __launch_bounds__(512, 1)
k_lin2a(const float4* __restrict__ W2) {
    extern __shared__ float4 smem4[];
    float4* Ws = smem4;               // [128][33] (per chunk)
    float4* As = smem4 + 128 * 33;    // [128][33]
    int t = threadIdx.x;
    int cg = t & 31, rg = t >> 5;     // cols {cg,+32,+64,+96}; rows rg*8..+7

    for (int tile = blockIdx.x; tile < NTILES; tile += gridDim.x) {
        int base = tile * 128;
        float acc[8][4];
#pragma unroll
        for (int r = 0; r < 8; r++)
#pragma unroll
            for (int j = 0; j < 4; j++) acc[r][j] = 0.f;

        for (int kk = 0; kk < 2; kk++) {
            __syncthreads();
            for (int i = t; i < 128 * 32; i += 512) {
                int c = i >> 5, k = i & 31;
                Ws[c * 33 + k] = __ldg(&W2[c * 64 + kk * 32 + k]);
            }
            for (int i = t; i < 128 * 32; i += 512) {
                int r = i >> 5, k = i & 31;
                int row = base + r;
                float4 v = make_float4(0.f, 0.f, 0.f, 0.f);
                if (row < N_NODES) v = g_y1[(size_t)row * 64 + kk * 32 + k];
                As[r * 33 + k] = v;
            }
            __syncthreads();

#pragma unroll 2
            for (int k4 = 0; k4 < 32; k4++) {
                float4 w0 = Ws[(cg     ) * 33 + k4];
                float4 w1 = Ws[(cg + 32) * 33 + k4];
                float4 w2 = Ws[(cg + 64) * 33 + k4];
                float4 w3 = Ws[(cg + 96) * 33 + k4];
#pragma unroll
                for (int r = 0; r < 8; r++) {
                    float4 a = As[(rg * 8 + r) * 33 + k4];
                    acc[r][0] += a.x * w0.x + a.y * w0.y + a.z * w0.z + a.w * w0.w;
                    acc[r][1] += a.x * w1.x + a.y * w1.y + a.z * w1.z + a.w * w1.w;
                    acc[r][2] += a.x * w2.x + a.y * w2.y + a.z * w2.z + a.w * w2.w;
                    acc[r][3] += a.x * w3.x + a.y * w3.y + a.z * w3.z + a.w * w3.w;
                }
            }
        }

        float* Z = (float*)g_z;
#pragma unroll
        for (int r = 0; r < 8; r++) {
            int row = base + rg * 8 + r;
            if (row < N_NODES) {
#pragma unroll
                for (int j = 0; j < 4; j++)
                    Z[(size_t)row * 128 + cg + 32 * j] = acc[r][j];
            }
        }
    }
}

// ---------------- final: out = normalize(agg2*invd + b2) * exp(ls), warp per row ----------------
__global__ void k_final(const float4* __restrict__ b2, const float* __restrict__ logit,
                        float4* __restrict__ out) {
    int gt = blockIdx.x * blockDim.x + threadIdx.x;
    int row = gt >> 5, lane = gt & 31;
    if (row >= N_NODES) return;
    float invd = g_invd[row];
    float4 v = g_agg2[(size_t)row * 32 + lane];
    float4 bb = __ldg(&b2[lane]);
    v.x = v.x * invd + bb.x;
    v.y = v.y * invd + bb.y;
    v.z = v.z * invd + bb.z;
    v.w = v.w * invd + bb.w;
    float ss = v.x * v.x + v.y * v.y + v.z * v.z + v.w * v.w;
#pragma unroll
    for (int off = 16; off > 0; off >>= 1)
        ss += __shfl_xor_sync(0xffffffffu, ss, off);
    float sca = expf(__ldg(logit)) / fmaxf(sqrtf(ss), 1e-12f);
    v.x *= sca; v.y *= sca; v.z *= sca; v.w *= sca;
    out[(size_t)row * 32 + lane] = v;
}

// ---------------- launch ----------------
extern "C" void kernel_launch(void* const* d_in, const int* in_sizes, int n_in,
                              void* d_out, int out_size) {
    const void *px = 0, *pei = 0, *pW1 = 0, *pb1 = 0, *pW2 = 0, *pb2 = 0, *pls = 0;
    int nW = 0;
    for (int i = 0; i < n_in; i++) {
        switch (in_sizes[i]) {
            case 6400000: px = d_in[i]; break;
            case 1280000: pei = d_in[i]; break;
            case 32768:   if (nW++ == 0) pW1 = d_in[i]; else pW2 = d_in[i]; break;
            case 256:     pb1 = d_in[i]; break;
            case 128:     pb2 = d_in[i]; break;
            case 1:       pls = d_in[i]; break;
            default: break;
        }
    }
    if (!px)  px  = d_in[0];
    if (!pei) pei = d_in[1];
    if (!pW1) pW1 = d_in[2];
    if (!pb1) pb1 = d_in[3];
    if (!pW2) pW2 = d_in[4];
    if (!pb2) pb2 = d_in[5];
    if (!pls) pls = d_in[6];

    const float4* x  = (const float4*)px;
    const int*    ei = (const int*)pei;
    const float4* W1 = (const float4*)pW1;
    const float*  b1 = (const float*)pb1;
    const float4* W2 = (const float4*)pW2;
    const float4* b2 = (const float4*)pb2;
    const float*  ls = (const float*)pls;
    float4*       out = (float4*)d_out;

    cudaFuncSetAttribute(k_lin1,  cudaFuncAttributeMaxDynamicSharedMemorySize, SMEM_LIN1);
    cudaFuncSetAttribute(k_lin2a, cudaFuncAttributeMaxDynamicSharedMemorySize, SMEM_LIN2);

    int eblocks = (N_EDGES + 255) / 256;
    int nblocks = (N_NODES + 255) / 256;
    int gblocks = (N_NODES * 32 + 255) / 256;   // warp per node

    k_detect<<<1, 32>>>(ei);
    k_zero<<<nblocks, 256>>>();
    k_deg<<<eblocks, 256>>>(ei);
    k_invdeg<<<nblocks, 256>>>();
    k_scan<<<1, 1024>>>();
    k_fill<<<eblocks, 256>>>(ei);
    k_gather1<<<gblocks, 256>>>(x);
    k_lin1<<<148, 512, SMEM_LIN1>>>(W1, b1);
    k_lin2a<<<148, 512, SMEM_LIN2>>>(W2);
    k_gather2<<<gblocks, 256>>>();
    k_final<<<gblocks, 256>>>(b2, ls, out);
}

// round 7
// speedup vs baseline: 2.9016x; 1.0080x over previous
#include <cuda_runtime.h>
#include <math.h>

#define N_NODES 50000
#define N_EDGES 640000
// dims: 128 -> 256 -> 128

// ---------------- scratch (device-code-only references; never host args) ----------------
__device__ float4 g_agg1[N_NODES * 32];   // mean-aggregated x (incl self), invd pre-applied
__device__ float4 g_y1  [N_NODES * 64];   // relu(lin1)
__device__ float4 g_z   [N_NODES * 32];   // y1 @ W2^T (pre-aggregation)
__device__ int    g_dege[N_NODES];
__device__ int    g_rowstart[N_NODES + 1];
__device__ int    g_cursor[N_NODES];
__device__ int    g_csr[N_EDGES];
__device__ int    g_idx64;

// ---------------- packed f32x2 helpers ----------------
union F4U { float4 f; unsigned long long u[2]; };

__device__ __forceinline__ void ffma2(unsigned long long& d, unsigned long long a,
                                      unsigned long long b) {
    asm("fma.rn.f32x2 %0, %1, %2, %0;" : "+l"(d) : "l"(a), "l"(b));
}
__device__ __forceinline__ float f2sum(unsigned long long v) {
    unsigned lo, hi;
    asm("mov.b64 {%0, %1}, %2;" : "=r"(lo), "=r"(hi) : "l"(v));
    return __uint_as_float(lo) + __uint_as_float(hi);
}

// ---------------- edge index accessor (int32 or int64 storage) ----------------
__device__ __forceinline__ int edge_at(const int* __restrict__ ei, int which, int e) {
    if (g_idx64) return ei[((size_t)which * N_EDGES + (size_t)e) * 2];
    return ei[which * N_EDGES + e];
}

// ---------------- setup: zero counters + dtype detect ----------------
__global__ void k_setup(const int* __restrict__ ei) {
    int i = blockIdx.x * blockDim.x + threadIdx.x;
    if (i < N_NODES) { g_dege[i] = 0; g_cursor[i] = 0; }
    if (i == 0) {
        int orr = 0;
#pragma unroll
        for (int j = 0; j < 16; j++) orr |= ei[2 * j + 1];
        g_idx64 = (orr == 0) ? 1 : 0;
    }
}

__global__ void k_deg(const int* __restrict__ ei) {
    int e = blockIdx.x * blockDim.x + threadIdx.x;
    if (e < N_EDGES) atomicAdd(&g_dege[edge_at(ei, 1, e)], 1);
}

// ---------------- exclusive scan of g_dege -> g_rowstart (single block, 1024 thr) ----------------
__global__ void __launch_bounds__(1024, 1) k_scan() {
    __shared__ int wsum[32];
    __shared__ int s_carry;
    int t = threadIdx.x, lane = t & 31, w = t >> 5;
    if (t == 0) { s_carry = 0; g_rowstart[N_NODES] = N_EDGES; }
    __syncthreads();
    for (int base = 0; base < N_NODES; base += 1024) {
        int i = base + t;
        int v = (i < N_NODES) ? g_dege[i] : 0;
        int x = v;
#pragma unroll
        for (int off = 1; off < 32; off <<= 1) {
            int y = __shfl_up_sync(0xffffffffu, x, off);
            if (lane >= off) x += y;
        }
        if (lane == 31) wsum[w] = x;
        __syncthreads();
        if (t < 32) {
            int s = wsum[t];
#pragma unroll
            for (int off = 1; off < 32; off <<= 1) {
                int y = __shfl_up_sync(0xffffffffu, s, off);
                if (t >= off) s += y;
            }
            wsum[t] = s;
        }
        __syncthreads();
        int incl = x + (w > 0 ? wsum[w - 1] : 0);
        int carry = s_carry;
        if (i < N_NODES) g_rowstart[i] = carry + incl - v;
        int total = wsum[31];
        __syncthreads();
        if (t == 0) s_carry = carry + total;
        __syncthreads();
    }
}

__global__ void k_fill(const int* __restrict__ ei) {
    int e = blockIdx.x * blockDim.x + threadIdx.x;
    if (e >= N_EDGES) return;
    int s = edge_at(ei, 0, e);
    int d = edge_at(ei, 1, e);
    int off = atomicAdd(&g_cursor[d], 1);
    g_csr[g_rowstart[d] + off] = s;
}

// ---------------- gather1: agg1[d] = mean(x[d] + sum_{s in N(d)} x[s]) ----------------
__global__ void k_gather1(const float4* __restrict__ x) {
    int gt = blockIdx.x * blockDim.x + threadIdx.x;
    int d = gt >> 5, lane = gt & 31;
    if (d >= N_NODES) return;
    int s0 = g_rowstart[d], s1 = g_rowstart[d + 1];
    float4 acc = __ldg(&x[(size_t)d * 32 + lane]);
    for (int i = s0; i < s1; i += 32) {
        int lim = s1 - i;
#pragma unroll
        for (int j = 0; j < 32; j++) {
            if (j < lim) {
                int s = __ldg(&g_csr[i + j]);
                float4 v = __ldg(&x[(size_t)s * 32 + lane]);
                acc.x += v.x; acc.y += v.y; acc.z += v.z; acc.w += v.w;
            }
        }
    }
    float invd = 1.0f / (float)(s1 - s0 + 1);
    acc.x *= invd; acc.y *= invd; acc.z *= invd; acc.w *= invd;
    g_agg1[(size_t)d * 32 + lane] = acc;
}

// ---------------- lin1: y1 = relu(agg1 @ W1^T + b1), 128 -> 256, FFMA2 ----------------
// Tile 64 rows x 256 cols, 512 threads: cg=t&63 (cols cg,+64,+128,+192), rg=t>>6 (8x8 rows).
// acc2[r][j] u64 = even/odd-K partials. W resident in smem.
#define NTILES1 ((N_NODES + 63) / 64)     // 782
#define SMEM_LIN1 ((256 * 33 + 64 * 33) * 16)
__global__ void __launch_bounds__(512, 1)
k_lin1(const float4* __restrict__ W1, const float* __restrict__ b1) {
    extern __shared__ float4 smem4[];
    float4* Ws = smem4;               // [256][33]
    float4* As = smem4 + 256 * 33;    // [64][33]
    int t = threadIdx.x;
    int cg = t & 63, rg = t >> 6;

    for (int i = t; i < 256 * 32; i += 512)
        Ws[(i >> 5) * 33 + (i & 31)] = __ldg(&W1[i]);
    float bb[4];
#pragma unroll
    for (int j = 0; j < 4; j++) bb[j] = __ldg(&b1[cg + 64 * j]);

    for (int tile = blockIdx.x; tile < NTILES1; tile += gridDim.x) {
        int base = tile * 64;
        __syncthreads();
        for (int i = t; i < 64 * 32; i += 512) {
            int r = i >> 5, k = i & 31;
            int row = base + r;
            float4 v = make_float4(0.f, 0.f, 0.f, 0.f);
            if (row < N_NODES) v = g_agg1[(size_t)row * 32 + k];
            As[r * 33 + k] = v;
        }
        __syncthreads();

        unsigned long long acc2[8][4];
#pragma unroll
        for (int r = 0; r < 8; r++)
#pragma unroll
            for (int j = 0; j < 4; j++) acc2[r][j] = 0ull;

#pragma unroll 2
        for (int k4 = 0; k4 < 32; k4++) {
            F4U w0, w1, w2, w3;
            w0.f = Ws[(cg      ) * 33 + k4];
            w1.f = Ws[(cg +  64) * 33 + k4];
            w2.f = Ws[(cg + 128) * 33 + k4];
            w3.f = Ws[(cg + 192) * 33 + k4];
#pragma unroll
            for (int r = 0; r < 8; r++) {
                F4U a; a.f = As[(rg * 8 + r) * 33 + k4];
                ffma2(acc2[r][0], a.u[0], w0.u[0]);
                ffma2(acc2[r][0], a.u[1], w0.u[1]);
                ffma2(acc2[r][1], a.u[0], w1.u[0]);
                ffma2(acc2[r][1], a.u[1], w1.u[1]);
                ffma2(acc2[r][2], a.u[0], w2.u[0]);
                ffma2(acc2[r][2], a.u[1], w2.u[1]);
                ffma2(acc2[r][3], a.u[0], w3.u[0]);
                ffma2(acc2[r][3], a.u[1], w3.u[1]);
            }
        }

        float* Y = (float*)g_y1;
#pragma unroll
        for (int r = 0; r < 8; r++) {
            int row = base + rg * 8 + r;
            if (row < N_NODES) {
#pragma unroll
                for (int j = 0; j < 4; j++)
                    Y[(size_t)row * 256 + cg + 64 * j] = fmaxf(f2sum(acc2[r][j]) + bb[j], 0.f);
            }
        }
    }
}

// ---------------- lin2a: z = y1 @ W2^T (no bias), 256 -> 128, FFMA2 ----------------
// Tile 128 rows x 128 cols, 512 threads: cg=t&31 (cols cg,+32,+64,+96), rg=t>>5 (16x8 rows).
// Full W2 resident [128][65] f4; A chunked over K (2 x 128).
#define NTILES2 ((N_NODES + 127) / 128)   // 391
#define SMEM_LIN2 ((128 * 65 + 128 * 33) * 16)
__global__ void __launch_bounds__(512, 1)
k_lin2a(const float4* __restrict__ W2) {
    extern __shared__ float4 smem4[];
    float4* Ws = smem4;               // [128][65]  (all 64 f4 of K=256)
    float4* As = smem4 + 128 * 65;    // [128][33]  (one 128-wide K chunk)
    int t = threadIdx.x;
    int cg = t & 31, rg = t >> 5;

    for (int i = t; i < 128 * 64; i += 512)
        Ws[(i >> 6) * 65 + (i & 63)] = __ldg(&W2[i]);

    for (int tile = blockIdx.x; tile < NTILES2; tile += gridDim.x) {
        int base = tile * 128;
        unsigned long long acc2[8][4];
#pragma unroll
        for (int r = 0; r < 8; r++)
#pragma unroll
            for (int j = 0; j < 4; j++) acc2[r][j] = 0ull;

        for (int kk = 0; kk < 2; kk++) {
            __syncthreads();
            for (int i = t; i < 128 * 32; i += 512) {
                int r = i >> 5, k = i & 31;
                int row = base + r;
                float4 v = make_float4(0.f, 0.f, 0.f, 0.f);
                if (row < N_NODES) v = g_y1[(size_t)row * 64 + kk * 32 + k];
                As[r * 33 + k] = v;
            }
            __syncthreads();

#pragma unroll 2
            for (int k4 = 0; k4 < 32; k4++) {
                F4U w0, w1, w2, w3;
                w0.f = Ws[(cg     ) * 65 + kk * 32 + k4];
                w1.f = Ws[(cg + 32) * 65 + kk * 32 + k4];
                w2.f = Ws[(cg + 64) * 65 + kk * 32 + k4];
                w3.f = Ws[(cg + 96) * 65 + kk * 32 + k4];
#pragma unroll
                for (int r = 0; r < 8; r++) {
                    F4U a; a.f = As[(rg * 8 + r) * 33 + k4];
                    ffma2(acc2[r][0], a.u[0], w0.u[0]);
                    ffma2(acc2[r][0], a.u[1], w0.u[1]);
                    ffma2(acc2[r][1], a.u[0], w1.u[0]);
                    ffma2(acc2[r][1], a.u[1], w1.u[1]);
                    ffma2(acc2[r][2], a.u[0], w2.u[0]);
                    ffma2(acc2[r][2], a.u[1], w2.u[1]);
                    ffma2(acc2[r][3], a.u[0], w3.u[0]);
                    ffma2(acc2[r][3], a.u[1], w3.u[1]);
                }
            }
        }

        float* Z = (float*)g_z;
#pragma unroll
        for (int r = 0; r < 8; r++) {
            int row = base + rg * 8 + r;
            if (row < N_NODES) {
#pragma unroll
                for (int j = 0; j < 4; j++)
                    Z[(size_t)row * 128 + cg + 32 * j] = f2sum(acc2[r][j]);
            }
        }
    }
}

// ---------------- gather2 + final: out = normalize(mean(z) + b2) * exp(ls) ----------------
__global__ void k_gather2f(const float4* __restrict__ b2, const float* __restrict__ logit,
                           float4* __restrict__ out) {
    int gt = blockIdx.x * blockDim.x + threadIdx.x;
    int d = gt >> 5, lane = gt & 31;
    if (d >= N_NODES) return;
    int s0 = g_rowstart[d], s1 = g_rowstart[d + 1];
    float4 acc = g_z[(size_t)d * 32 + lane];
    for (int i = s0; i < s1; i += 32) {
        int lim = s1 - i;
#pragma unroll
        for (int j = 0; j < 32; j++) {
            if (j < lim) {
                int s = __ldg(&g_csr[i + j]);
                float4 v = g_z[(size_t)s * 32 + lane];
                acc.x += v.x; acc.y += v.y; acc.z += v.z; acc.w += v.w;
            }
        }
    }
    float invd = 1.0f / (float)(s1 - s0 + 1);
    float4 bb = __ldg(&b2[lane]);
    acc.x = acc.x * invd + bb.x;
    acc.y = acc.y * invd + bb.y;
    acc.z = acc.z * invd + bb.z;
    acc.w = acc.w * invd + bb.w;
    float ss = acc.x * acc.x + acc.y * acc.y + acc.z * acc.z + acc.w * acc.w;
#pragma unroll
    for (int off = 16; off > 0; off >>= 1)
        ss += __shfl_xor_sync(0xffffffffu, ss, off);
    float sca = expf(__ldg(logit)) / fmaxf(sqrtf(ss), 1e-12f);
    acc.x *= sca; acc.y *= sca; acc.z *= sca; acc.w *= sca;
    out[(size_t)d * 32 + lane] = acc;
}

// ---------------- launch ----------------
extern "C" void kernel_launch(void* const* d_in, const int* in_sizes, int n_in,
                              void* d_out, int out_size) {
    const void *px = 0, *pei = 0, *pW1 = 0, *pb1 = 0, *pW2 = 0, *pb2 = 0, *pls = 0;
    int nW = 0;
    for (int i = 0; i < n_in; i++) {
        switch (in_sizes[i]) {
            case 6400000: px = d_in[i]; break;
            case 1280000: pei = d_in[i]; break;
            case 32768:   if (nW++ == 0) pW1 = d_in[i]; else pW2 = d_in[i]; break;
            case 256:     pb1 = d_in[i]; break;
            case 128:     pb2 = d_in[i]; break;
            case 1:       pls = d_in[i]; break;
            default: break;
        }
    }
    if (!px)  px  = d_in[0];
    if (!pei) pei = d_in[1];
    if (!pW1) pW1 = d_in[2];
    if (!pb1) pb1 = d_in[3];
    if (!pW2) pW2 = d_in[4];
    if (!pb2) pb2 = d_in[5];
    if (!pls) pls = d_in[6];

    const float4* x  = (const float4*)px;
    const int*    ei = (const int*)pei;
    const float4* W1 = (const float4*)pW1;
    const float*  b1 = (const float*)pb1;
    const float4* W2 = (const float4*)pW2;
    const float4* b2 = (const float4*)pb2;
    const float*  ls = (const float*)pls;
    float4*       out = (float4*)d_out;

    cudaFuncSetAttribute(k_lin1,  cudaFuncAttributeMaxDynamicSharedMemorySize, SMEM_LIN1);
    cudaFuncSetAttribute(k_lin2a, cudaFuncAttributeMaxDynamicSharedMemorySize, SMEM_LIN2);

    int eblocks = (N_EDGES + 255) / 256;
    int nblocks = (N_NODES + 255) / 256;
    int gblocks = (N_NODES * 32 + 255) / 256;   // warp per node

    k_setup<<<nblocks, 256>>>(ei);
    k_deg<<<eblocks, 256>>>(ei);
    k_scan<<<1, 1024>>>();
    k_fill<<<eblocks, 256>>>(ei);
    k_gather1<<<gblocks, 256>>>(x);
    k_lin1<<<148, 512, SMEM_LIN1>>>(W1, b1);
    k_lin2a<<<148, 512, SMEM_LIN2>>>(W2);
    k_gather2f<<<gblocks, 256>>>(b2, ls, out);
}

// round 8
// speedup vs baseline: 3.0527x; 1.0521x over previous
#include <cuda_runtime.h>
#include <math.h>

#define N_NODES 50000
#define N_EDGES 640000
// dims: 128 -> 256 -> 128

// ---------------- scratch (device-code-only references; never host args) ----------------
__device__ float4 g_agg1[N_NODES * 32];   // mean-aggregated x (incl self)
__device__ float4 g_y1  [N_NODES * 64];   // relu(lin1)
__device__ float4 g_z   [N_NODES * 32];   // y1 @ W2^T (pre-aggregation)
__device__ int    g_dege[N_NODES];
__device__ int    g_rowstart[N_NODES + 1];
__device__ int    g_cursor[N_NODES];      // seeded with rowstart by k_scan
__device__ int    g_csr[N_EDGES];
__device__ int    g_idx64;

// ---------------- packed f32x2 helpers ----------------
union F4U { float4 f; unsigned long long u[2]; };

__device__ __forceinline__ void ffma2(unsigned long long& d, unsigned long long a,
                                      unsigned long long b) {
    asm("fma.rn.f32x2 %0, %1, %2, %0;" : "+l"(d) : "l"(a), "l"(b));
}
__device__ __forceinline__ float f2sum(unsigned long long v) {
    unsigned lo, hi;
    asm("mov.b64 {%0, %1}, %2;" : "=r"(lo), "=r"(hi) : "l"(v));
    return __uint_as_float(lo) + __uint_as_float(hi);
}

// ---------------- edge index accessor (int32 or int64 storage) ----------------
__device__ __forceinline__ int edge_at(const int* __restrict__ ei, int which, int e) {
    if (g_idx64) return ei[((size_t)which * N_EDGES + (size_t)e) * 2];
    return ei[which * N_EDGES + e];
}

__global__ void k_setup(const int* __restrict__ ei) {
    int i = blockIdx.x * blockDim.x + threadIdx.x;
    if (i < N_NODES) g_dege[i] = 0;
    if (i == 0) {
        int orr = 0;
#pragma unroll
        for (int j = 0; j < 16; j++) orr |= ei[2 * j + 1];
        g_idx64 = (orr == 0) ? 1 : 0;
    }
}

__global__ void k_deg(const int* __restrict__ ei) {
    int e = blockIdx.x * blockDim.x + threadIdx.x;
    if (e < N_EDGES) atomicAdd(&g_dege[edge_at(ei, 1, e)], 1);
}

// ---------------- exclusive scan of g_dege -> g_rowstart (+ seed cursor) ----------------
__global__ void __launch_bounds__(1024, 1) k_scan() {
    __shared__ int wsum[32];
    __shared__ int s_carry;
    int t = threadIdx.x, lane = t & 31, w = t >> 5;
    if (t == 0) { s_carry = 0; g_rowstart[N_NODES] = N_EDGES; }
    __syncthreads();
    for (int base = 0; base < N_NODES; base += 1024) {
        int i = base + t;
        int v = (i < N_NODES) ? g_dege[i] : 0;
        int x = v;
#pragma unroll
        for (int off = 1; off < 32; off <<= 1) {
            int y = __shfl_up_sync(0xffffffffu, x, off);
            if (lane >= off) x += y;
        }
        if (lane == 31) wsum[w] = x;
        __syncthreads();
        if (t < 32) {
            int s = wsum[t];
#pragma unroll
            for (int off = 1; off < 32; off <<= 1) {
                int y = __shfl_up_sync(0xffffffffu, s, off);
                if (t >= off) s += y;
            }
            wsum[t] = s;
        }
        __syncthreads();
        int incl = x + (w > 0 ? wsum[w - 1] : 0);
        int carry = s_carry;
        if (i < N_NODES) {
            int rs = carry + incl - v;
            g_rowstart[i] = rs;
            g_cursor[i] = rs;
        }
        int total = wsum[31];
        __syncthreads();
        if (t == 0) s_carry = carry + total;
        __syncthreads();
    }
}

__global__ void k_fill(const int* __restrict__ ei) {
    int e = blockIdx.x * blockDim.x + threadIdx.x;
    if (e >= N_EDGES) return;
    int s = edge_at(ei, 0, e);
    int d = edge_at(ei, 1, e);
    int off = atomicAdd(&g_cursor[d], 1);   // cursor pre-seeded with rowstart
    g_csr[off] = s;
}

// ---------------- gather1: agg1[d] = mean(x[d] + sum_{s in N(d)} x[s]) ----------------
__global__ void k_gather1(const float4* __restrict__ x) {
    int gt = blockIdx.x * blockDim.x + threadIdx.x;
    int d = gt >> 5, lane = gt & 31;
    if (d >= N_NODES) return;
    int s0 = g_rowstart[d], s1 = g_rowstart[d + 1];
    float4 acc = __ldg(&x[(size_t)d * 32 + lane]);
    for (int i = s0; i < s1; i += 32) {
        int lim = s1 - i;
#pragma unroll
        for (int j = 0; j < 32; j++) {
            if (j < lim) {
                int s = __ldg(&g_csr[i + j]);
                float4 v = __ldg(&x[(size_t)s * 32 + lane]);
                acc.x += v.x; acc.y += v.y; acc.z += v.z; acc.w += v.w;
            }
        }
    }
    float invd = 1.0f / (float)(s1 - s0 + 1);
    acc.x *= invd; acc.y *= invd; acc.z *= invd; acc.w *= invd;
    g_agg1[(size_t)d * 32 + lane] = acc;
}

// ---------------- lin1: y1 = relu(agg1 @ W1^T + b1), 128 -> 256 ----------------
// 256 threads; tile 64 rows x 256 cols; thread = 8r x 8c; K packed into FFMA2.
// cg = t&31 (cols cg+32c), rg = t>>5 (rows rg*8+r). W-loads conflict-free
// (stride 33 f4 -> lane stride 4 banks), A-loads warp-broadcast.
#define NTILES1 ((N_NODES + 63) / 64)     // 782
#define SMEM_LIN1 ((256 * 33 + 64 * 33) * 16)
__global__ void __launch_bounds__(256, 1)
k_lin1(const float4* __restrict__ W1, const float* __restrict__ b1) {
    extern __shared__ float4 smem4[];
    float4* Ws = smem4;               // [256][33]
    float4* As = smem4 + 256 * 33;    // [64][33]
    int t = threadIdx.x;
    int cg = t & 31, rg = t >> 5;

    for (int i = t; i < 256 * 32; i += 256)
        Ws[(i >> 5) * 33 + (i & 31)] = __ldg(&W1[i]);
    float bb[8];
#pragma unroll
    for (int c = 0; c < 8; c++) bb[c] = __ldg(&b1[cg + 32 * c]);

    for (int tile = blockIdx.x; tile < NTILES1; tile += gridDim.x) {
        int base = tile * 64;
        __syncthreads();
        for (int i = t; i < 64 * 32; i += 256) {
            int r = i >> 5, k = i & 31;
            int row = base + r;
            float4 v = make_float4(0.f, 0.f, 0.f, 0.f);
            if (row < N_NODES) v = g_agg1[(size_t)row * 32 + k];
            As[r * 33 + k] = v;
        }
        __syncthreads();

        unsigned long long acc2[8][8];
#pragma unroll
        for (int r = 0; r < 8; r++)
#pragma unroll
            for (int c = 0; c < 8; c++) acc2[r][c] = 0ull;

        for (int k4 = 0; k4 < 32; k4++) {
            F4U a[8];
#pragma unroll
            for (int r = 0; r < 8; r++) a[r].f = As[(rg * 8 + r) * 33 + k4];
#pragma unroll
            for (int c = 0; c < 8; c++) {
                F4U w; w.f = Ws[(cg + 32 * c) * 33 + k4];
#pragma unroll
                for (int r = 0; r < 8; r++) {
                    ffma2(acc2[r][c], a[r].u[0], w.u[0]);
                    ffma2(acc2[r][c], a[r].u[1], w.u[1]);
                }
            }
        }

        float* Y = (float*)g_y1;
#pragma unroll
        for (int r = 0; r < 8; r++) {
            int row = base + rg * 8 + r;
            if (row < N_NODES) {
#pragma unroll
                for (int c = 0; c < 8; c++)
                    Y[(size_t)row * 256 + cg + 32 * c] = fmaxf(f2sum(acc2[r][c]) + bb[c], 0.f);
            }
        }
    }
}

// ---------------- lin2a: z = y1 @ W2^T (no bias), 256 -> 128 ----------------
// 256 threads; tile 128 rows x 128 cols; thread = 8r x 8c; K=256 in 2 chunks.
// cg = t&15 (cols cg+16c), rg = t>>4 (rows rg*8+r).
#define NTILES2 ((N_NODES + 127) / 128)   // 391
#define SMEM_LIN2 ((128 * 65 + 128 * 33) * 16)
__global__ void __launch_bounds__(256, 1)
k_lin2a(const float4* __restrict__ W2) {
    extern __shared__ float4 smem4[];
    float4* Ws = smem4;               // [128][65]  (full K=256 = 64 f4)
    float4* As = smem4 + 128 * 65;    // [128][33]  (one 128-wide K chunk)
    int t = threadIdx.x;
    int cg = t & 15, rg = t >> 4;

    for (int i = t; i < 128 * 64; i += 256)
        Ws[(i >> 6) * 65 + (i & 63)] = __ldg(&W2[i]);

    for (int tile = blockIdx.x; tile < NTILES2; tile += gridDim.x) {
        int base = tile * 128;
        unsigned long long acc2[8][8];
#pragma unroll
        for (int r = 0; r < 8; r++)
#pragma unroll
            for (int c = 0; c < 8; c++) acc2[r][c] = 0ull;

        for (int kk = 0; kk < 2; kk++) {
            __syncthreads();
            for (int i = t; i < 128 * 32; i += 256) {
                int r = i >> 5, k = i & 31;
                int row = base + r;
                float4 v = make_float4(0.f, 0.f, 0.f, 0.f);
                if (row < N_NODES) v = g_y1[(size_t)row * 64 + kk * 32 + k];
                As[r * 33 + k] = v;
            }
            __syncthreads();

            for (int k4 = 0; k4 < 32; k4++) {
                F4U a[8];
#pragma unroll
                for (int r = 0; r < 8; r++) a[r].f = As[(rg * 8 + r) * 33 + k4];
#pragma unroll
                for (int c = 0; c < 8; c++) {
                    F4U w; w.f = Ws[(cg + 16 * c) * 65 + kk * 32 + k4];
#pragma unroll
                    for (int r = 0; r < 8; r++) {
                        ffma2(acc2[r][c], a[r].u[0], w.u[0]);
                        ffma2(acc2[r][c], a[r].u[1], w.u[1]);
                    }
                }
            }
        }

        float* Z = (float*)g_z;
#pragma unroll
        for (int r = 0; r < 8; r++) {
            int row = base + rg * 8 + r;
            if (row < N_NODES) {
#pragma unroll
                for (int c = 0; c < 8; c++)
                    Z[(size_t)row * 128 + cg + 16 * c] = f2sum(acc2[r][c]);
            }
        }
    }
}

// ---------------- gather2 + final: out = normalize(mean(z) + b2) * exp(ls) ----------------
__global__ void k_gather2f(const float4* __restrict__ b2, const float* __restrict__ logit,
                           float4* __restrict__ out) {
    int gt = blockIdx.x * blockDim.x + threadIdx.x;
    int d = gt >> 5, lane = gt & 31;
    if (d >= N_NODES) return;
    int s0 = g_rowstart[d], s1 = g_rowstart[d + 1];
    float4 acc = g_z[(size_t)d * 32 + lane];
    for (int i = s0; i < s1; i += 32) {
        int lim = s1 - i;
#pragma unroll
        for (int j = 0; j < 32; j++) {
            if (j < lim) {
                int s = __ldg(&g_csr[i + j]);
                float4 v = g_z[(size_t)s * 32 + lane];
                acc.x += v.x; acc.y += v.y; acc.z += v.z; acc.w += v.w;
            }
        }
    }
    float invd = 1.0f / (float)(s1 - s0 + 1);
    float4 bb = __ldg(&b2[lane]);
    acc.x = acc.x * invd + bb.x;
    acc.y = acc.y * invd + bb.y;
    acc.z = acc.z * invd + bb.z;
    acc.w = acc.w * invd + bb.w;
    float ss = acc.x * acc.x + acc.y * acc.y + acc.z * acc.z + acc.w * acc.w;
#pragma unroll
    for (int off = 16; off > 0; off >>= 1)
        ss += __shfl_xor_sync(0xffffffffu, ss, off);
    float sca = expf(__ldg(logit)) / fmaxf(sqrtf(ss), 1e-12f);
    acc.x *= sca; acc.y *= sca; acc.z *= sca; acc.w *= sca;
    out[(size_t)d * 32 + lane] = acc;
}

// ---------------- launch ----------------
extern "C" void kernel_launch(void* const* d_in, const int* in_sizes, int n_in,
                              void* d_out, int out_size) {
    const void *px = 0, *pei = 0, *pW1 = 0, *pb1 = 0, *pW2 = 0, *pb2 = 0, *pls = 0;
    int nW = 0;
    for (int i = 0; i < n_in; i++) {
        switch (in_sizes[i]) {
            case 6400000: px = d_in[i]; break;
            case 1280000: pei = d_in[i]; break;
            case 32768:   if (nW++ == 0) pW1 = d_in[i]; else pW2 = d_in[i]; break;
            case 256:     pb1 = d_in[i]; break;
            case 128:     pb2 = d_in[i]; break;
            case 1:       pls = d_in[i]; break;
            default: break;
        }
    }
    if (!px)  px  = d_in[0];
    if (!pei) pei = d_in[1];
    if (!pW1) pW1 = d_in[2];
    if (!pb1) pb1 = d_in[3];
    if (!pW2) pW2 = d_in[4];
    if (!pb2) pb2 = d_in[5];
    if (!pls) pls = d_in[6];

    const float4* x  = (const float4*)px;
    const int*    ei = (const int*)pei;
    const float4* W1 = (const float4*)pW1;
    const float*  b1 = (const float*)pb1;
    const float4* W2 = (const float4*)pW2;
    const float4* b2 = (const float4*)pb2;
    const float*  ls = (const float*)pls;
    float4*       out = (float4*)d_out;

    cudaFuncSetAttribute(k_lin1,  cudaFuncAttributeMaxDynamicSharedMemorySize, SMEM_LIN1);
    cudaFuncSetAttribute(k_lin2a, cudaFuncAttributeMaxDynamicSharedMemorySize, SMEM_LIN2);

    int eblocks = (N_EDGES + 255) / 256;
    int nblocks = (N_NODES + 255) / 256;
    int gblocks = (N_NODES * 32 + 255) / 256;   // warp per node

    k_setup<<<nblocks, 256>>>(ei);
    k_deg<<<eblocks, 256>>>(ei);
    k_scan<<<1, 1024>>>();
    k_fill<<<eblocks, 256>>>(ei);
    k_gather1<<<gblocks, 256>>>(x);
    k_lin1<<<148, 256, SMEM_LIN1>>>(W1, b1);
    k_lin2a<<<148, 256, SMEM_LIN2>>>(W2);
    k_gather2f<<<gblocks, 256>>>(b2, ls, out);
}

// round 10
// speedup vs baseline: 3.5563x; 1.1649x over previous
#include <cuda_runtime.h>
#include <cuda_bf16.h>
#include <mma.h>
#include <math.h>
#include <cstdint>

using namespace nvcuda;

#define N_NODES 50000
#define N_EDGES 640000
#define N_PAD   50048   // 391 tiles * 128 rows
// dims: 128 -> 256 -> 128

// ---------------- scratch (device-code-only references; never host args) ----------------
__device__ float4   g_agg1[N_NODES * 32];    // mean-aggregated x (incl self), f32
__device__ unsigned g_y1h[N_NODES * 128];    // relu(lin1) bf16 hi plane, packed bf16x2
__device__ unsigned g_y1l[N_NODES * 128];    // residual lo plane
__device__ float    g_z  [N_PAD * 128];      // y1 @ W2^T (pre-agg), f32, padded rows
__device__ int      g_dege[N_NODES];
__device__ int      g_rowstart[N_NODES + 1];
__device__ int      g_cursor[N_NODES];
__device__ int      g_csr[N_EDGES];
__device__ int      g_idx64;

// bf16 hi/lo split of two floats, packed bf16x2 (x -> low half)
union U32B2 { unsigned u; __nv_bfloat162 b; };
__device__ __forceinline__ void split2(float f0, float f1, unsigned& hi, unsigned& lo) {
    U32B2 h, l;
    h.b = __floats2bfloat162_rn(f0, f1);
    l.b = __floats2bfloat162_rn(f0 - __bfloat162float(h.b.x), f1 - __bfloat162float(h.b.y));
    hi = h.u; lo = l.u;
}

// ---------------- edge index accessor (int32 or int64 storage) ----------------
__device__ __forceinline__ int edge_at(const int* __restrict__ ei, int which, int e) {
    if (g_idx64) return ei[((size_t)which * N_EDGES + (size_t)e) * 2];
    return ei[which * N_EDGES + e];
}

__global__ void k_setup(const int* __restrict__ ei) {
    int i = blockIdx.x * blockDim.x + threadIdx.x;
    if (i < N_NODES) g_dege[i] = 0;
    if (i == 0) {
        int orr = 0;
#pragma unroll
        for (int j = 0; j < 16; j++) orr |= ei[2 * j + 1];
        g_idx64 = (orr == 0) ? 1 : 0;
    }
}

__global__ void k_deg(const int* __restrict__ ei) {
    int e = blockIdx.x * blockDim.x + threadIdx.x;
    if (e < N_EDGES) atomicAdd(&g_dege[edge_at(ei, 1, e)], 1);
}

// ---------------- exclusive scan of g_dege -> g_rowstart (+ seed cursor) ----------------
__global__ void __launch_bounds__(1024, 1) k_scan() {
    __shared__ int wsum[32];
    __shared__ int s_carry;
    int t = threadIdx.x, lane = t & 31, w = t >> 5;
    if (t == 0) { s_carry = 0; g_rowstart[N_NODES] = N_EDGES; }
    __syncthreads();
    for (int base = 0; base < N_NODES; base += 1024) {
        int i = base + t;
        int v = (i < N_NODES) ? g_dege[i] : 0;
        int x = v;
#pragma unroll
        for (int off = 1; off < 32; off <<= 1) {
            int y = __shfl_up_sync(0xffffffffu, x, off);
            if (lane >= off) x += y;
        }
        if (lane == 31) wsum[w] = x;
        __syncthreads();
        if (t < 32) {
            int s = wsum[t];
#pragma unroll
            for (int off = 1; off < 32; off <<= 1) {
                int y = __shfl_up_sync(0xffffffffu, s, off);
                if (t >= off) s += y;
            }
            wsum[t] = s;
        }
        __syncthreads();
        int incl = x + (w > 0 ? wsum[w - 1] : 0);
        int carry = s_carry;
        if (i < N_NODES) {
            int rs = carry + incl - v;
            g_rowstart[i] = rs;
            g_cursor[i] = rs;
        }
        int total = wsum[31];
        __syncthreads();
        if (t == 0) s_carry = carry + total;
        __syncthreads();
    }
}

__global__ void k_fill(const int* __restrict__ ei) {
    int e = blockIdx.x * blockDim.x + threadIdx.x;
    if (e >= N_EDGES) return;
    int s = edge_at(ei, 0, e);
    int d = edge_at(ei, 1, e);
    int off = atomicAdd(&g_cursor[d], 1);
    g_csr[off] = s;
}

// ---------------- gather1: agg1[d] = mean(x[d] + sum_{s in N(d)} x[s]) ----------------
__global__ void k_gather1(const float4* __restrict__ x) {
    int gt = blockIdx.x * blockDim.x + threadIdx.x;
    int d = gt >> 5, lane = gt & 31;
    if (d >= N_NODES) return;
    int s0 = g_rowstart[d], s1 = g_rowstart[d + 1];
    float4 acc = __ldg(&x[(size_t)d * 32 + lane]);
    for (int i = s0; i < s1; i += 32) {
        int lim = s1 - i;
#pragma unroll
        for (int j = 0; j < 32; j++) {
            if (j < lim) {
                int s = __ldg(&g_csr[i + j]);
                float4 v = __ldg(&x[(size_t)s * 32 + lane]);
                acc.x += v.x; acc.y += v.y; acc.z += v.z; acc.w += v.w;
            }
        }
    }
    float invd = 1.0f / (float)(s1 - s0 + 1);
    acc.x *= invd; acc.y *= invd; acc.z *= invd; acc.w *= invd;
    g_agg1[(size_t)d * 32 + lane] = acc;
}

// ================= lin1: y1 = relu(agg1 @ W1^T + b1), 128->256, WMMA bf16 3-split =======
// smem: W1 hi/lo planes [256][136] bf16 (persistent), A hi/lo [128][136] bf16 per tile,
// A region reused as f32 staging [128][136] for the epilogue (one 128-col half at a time).
#define L1_LD 136
#define L1_WHI 0
#define L1_WLO (256 * L1_LD * 2)
#define L1_A   (2 * 256 * L1_LD * 2)
#define L1_AHI L1_A
#define L1_ALO (L1_A + 128 * L1_LD * 2)
#define L1_SMEM (L1_A + 2 * 128 * L1_LD * 2)    // 208896 bytes
#define L1_TILES ((N_NODES + 127) / 128)        // 391
__global__ void __launch_bounds__(256, 1)
k_lin1_mma(const float* __restrict__ W1, const float* __restrict__ b1) {
    extern __shared__ char smem[];
    __nv_bfloat16* Whi = (__nv_bfloat16*)(smem + L1_WHI);
    __nv_bfloat16* Wlo = (__nv_bfloat16*)(smem + L1_WLO);
    __nv_bfloat16* Ahi = (__nv_bfloat16*)(smem + L1_AHI);
    __nv_bfloat16* Alo = (__nv_bfloat16*)(smem + L1_ALO);
    float* stage = (float*)(smem + L1_A);       // [128][136] f32, overlays A planes
    int t = threadIdx.x, wid = t >> 5;
    int mg = wid & 3, cg = wid >> 2;            // warp: rows 32*mg..+31, cols 128*cg..+127

    // W1 [256][128] f32 -> bf16 hi/lo planes
    for (int i = t; i < 256 * 128; i += 256) {
        int n = i >> 7, k = i & 127;
        float w = __ldg(&W1[i]);
        __nv_bfloat16 hb = __float2bfloat16(w);
        Whi[n * L1_LD + k] = hb;
        Wlo[n * L1_LD + k] = __float2bfloat16(w - __bfloat162float(hb));
    }
    __syncthreads();

    for (int tile = blockIdx.x; tile < L1_TILES; tile += gridDim.x) {
        int base = tile * 128;
        // load + split A tile
        for (int i = t; i < 128 * 32; i += 256) {
            int r = i >> 5, k4 = i & 31;
            int row = base + r;
            float4 v = make_float4(0.f, 0.f, 0.f, 0.f);
            if (row < N_NODES) v = g_agg1[(size_t)row * 32 + k4];
            uint2 hp, lp;
            split2(v.x, v.y, hp.x, lp.x);
            split2(v.z, v.w, hp.y, lp.y);
            *(uint2*)(Ahi + r * L1_LD + 4 * k4) = hp;
            *(uint2*)(Alo + r * L1_LD + 4 * k4) = lp;
        }
        __syncthreads();

        wmma::fragment<wmma::accumulator, 16, 16, 16, float> acc[2][8];
#pragma unroll
        for (int m = 0; m < 2; m++)
#pragma unroll
            for (int n = 0; n < 8; n++) wmma::fill_fragment(acc[m][n], 0.f);

        int rows0 = mg * 32, cols0 = cg * 128;
#pragma unroll
        for (int ks = 0; ks < 8; ks++) {
            wmma::fragment<wmma::matrix_a, 16, 16, 16, __nv_bfloat16, wmma::row_major> ah[2], al[2];
#pragma unroll
            for (int m = 0; m < 2; m++) {
                wmma::load_matrix_sync(ah[m], Ahi + (rows0 + 16 * m) * L1_LD + ks * 16, L1_LD);
                wmma::load_matrix_sync(al[m], Alo + (rows0 + 16 * m) * L1_LD + ks * 16, L1_LD);
            }
#pragma unroll
            for (int n = 0; n < 8; n++) {
                wmma::fragment<wmma::matrix_b, 16, 16, 16, __nv_bfloat16, wmma::col_major> bh, bl;
                int col = cols0 + 16 * n;
                wmma::load_matrix_sync(bh, Whi + col * L1_LD + ks * 16, L1_LD);
                wmma::load_matrix_sync(bl, Wlo + col * L1_LD + ks * 16, L1_LD);
#pragma unroll
                for (int m = 0; m < 2; m++) {
                    wmma::mma_sync(acc[m][n], ah[m], bh, acc[m][n]);
                    wmma::mma_sync(acc[m][n], ah[m], bl, acc[m][n]);
                    wmma::mma_sync(acc[m][n], al[m], bh, acc[m][n]);
                }
            }
        }

        // epilogue: two 128-col halves through f32 staging (overlays A region)
#pragma unroll
        for (int h = 0; h < 2; h++) {
            __syncthreads();    // k-loop / previous half readers done
            if (cg == h) {
#pragma unroll
                for (int m = 0; m < 2; m++)
#pragma unroll
                    for (int n = 0; n < 8; n++)
                        wmma::store_matrix_sync(stage + (rows0 + 16 * m) * L1_LD + 16 * n,
                                                acc[m][n], L1_LD, wmma::mem_row_major);
            }
            __syncthreads();
            for (int i = t; i < 128 * 64; i += 256) {   // pairs of adjacent cols
                int r = i >> 6, p = i & 63, c = 2 * p;
                int row = base + r;
                if (row < N_NODES) {
                    float f0 = fmaxf(stage[r * L1_LD + c]     + __ldg(&b1[128 * h + c]),     0.f);
                    float f1 = fmaxf(stage[r * L1_LD + c + 1] + __ldg(&b1[128 * h + c + 1]), 0.f);
                    unsigned hp, lp;
                    split2(f0, f1, hp, lp);
                    g_y1h[(size_t)row * 128 + 64 * h + p] = hp;
                    g_y1l[(size_t)row * 128 + 64 * h + p] = lp;
                }
            }
        }
        __syncthreads();    // staging consumed before next tile's A-load
    }
}

// ================= lin2a: z = y1 @ W2^T, 256->128, WMMA bf16 3-split ====================
// W2 hi/lo planes [128][264] bf16 persistent; A (y1 planes) chunked over K (2 x 128).
// Epilogue stores straight to padded g_z (no bias here; bias folded into gather2f).
#define L2_LD 136
#define L2_WLD 264
#define L2_WHI 0
#define L2_WLO (128 * L2_WLD * 2)
#define L2_A   (2 * 128 * L2_WLD * 2)
#define L2_AHI L2_A
#define L2_ALO (L2_A + 128 * L2_LD * 2)
#define L2_SMEM (L2_A + 2 * 128 * L2_LD * 2)    // 204800 bytes
#define L2_TILES ((N_NODES + 127) / 128)        // 391
__global__ void __launch_bounds__(256, 1)
k_lin2_mma(const float* __restrict__ W2) {
    extern __shared__ char smem[];
    __nv_bfloat16* Whi = (__nv_bfloat16*)(smem + L2_WHI);
    __nv_bfloat16* Wlo = (__nv_bfloat16*)(smem + L2_WLO);
    __nv_bfloat16* Ahi = (__nv_bfloat16*)(smem + L2_AHI);
    __nv_bfloat16* Alo = (__nv_bfloat16*)(smem + L2_ALO);
    int t = threadIdx.x, wid = t >> 5;
    int mg = wid & 3, cg = wid >> 2;            // warp: rows 32*mg..+31, cols 64*cg..+63

    // W2 [128][256] f32 -> bf16 hi/lo planes
    for (int i = t; i < 128 * 256; i += 256) {
        int n = i >> 8, k = i & 255;
        float w = __ldg(&W2[i]);
        __nv_bfloat16 hb = __float2bfloat16(w);
        Whi[n * L2_WLD + k] = hb;
        Wlo[n * L2_WLD + k] = __float2bfloat16(w - __bfloat162float(hb));
    }
    __syncthreads();

    for (int tile = blockIdx.x; tile < L2_TILES; tile += gridDim.x) {
        int base = tile * 128;
        wmma::fragment<wmma::accumulator, 16, 16, 16, float> acc[2][4];
#pragma unroll
        for (int m = 0; m < 2; m++)
#pragma unroll
            for (int n = 0; n < 4; n++) wmma::fill_fragment(acc[m][n], 0.f);

        int rows0 = mg * 32, cols0 = cg * 64;
        for (int kc = 0; kc < 2; kc++) {
            __syncthreads();    // previous chunk readers done
            for (int i = t; i < 128 * 64; i += 256) {   // u32 = bf16x2 pair
                int r = i >> 6, q = i & 63;
                int row = base + r;
                unsigned hp = 0u, lp = 0u;
                if (row < N_NODES) {
                    hp = g_y1h[(size_t)row * 128 + 64 * kc + q];
                    lp = g_y1l[(size_t)row * 128 + 64 * kc + q];
                }
                *(unsigned*)(Ahi + r * L2_LD + 2 * q) = hp;
                *(unsigned*)(Alo + r * L2_LD + 2 * q) = lp;
            }
            __syncthreads();

#pragma unroll
            for (int ks = 0; ks < 8; ks++) {
                wmma::fragment<wmma::matrix_a, 16, 16, 16, __nv_bfloat16, wmma::row_major> ah[2], al[2];
#pragma unroll
                for (int m = 0; m < 2; m++) {
                    wmma::load_matrix_sync(ah[m], Ahi + (rows0 + 16 * m) * L2_LD + ks * 16, L2_LD);
                    wmma::load_matrix_sync(al[m], Alo + (rows0 + 16 * m) * L2_LD + ks * 16, L2_LD);
                }
                int kglob = 128 * kc + 16 * ks;
#pragma unroll
                for (int n = 0; n < 4; n++) {
                    wmma::fragment<wmma::matrix_b, 16, 16, 16, __nv_bfloat16, wmma::col_major> bh, bl;
                    int col = cols0 + 16 * n;
                    wmma::load_matrix_sync(bh, Whi + col * L2_WLD + kglob, L2_WLD);
                    wmma::load_matrix_sync(bl, Wlo + col * L2_WLD + kglob, L2_WLD);
#pragma unroll
                    for (int m = 0; m < 2; m++) {
                        wmma::mma_sync(acc[m][n], ah[m], bh, acc[m][n]);
                        wmma::mma_sync(acc[m][n], ah[m], bl, acc[m][n]);
                        wmma::mma_sync(acc[m][n], al[m], bh, acc[m][n]);
                    }
                }
            }
        }

        // epilogue: straight to padded g_z (rows >= N_NODES land in pad, never read)
#pragma unroll
        for (int m = 0; m < 2; m++)
#pragma unroll
            for (int n = 0; n < 4; n++)
                wmma::store_matrix_sync(g_z + (size_t)(base + rows0 + 16 * m) * 128 + cols0 + 16 * n,
                                        acc[m][n], 128, wmma::mem_row_major);
    }
}

// ---------------- gather2 + final: out = normalize(mean(z) + b2) * exp(ls) ----------------
__global__ void k_gather2f(const float4* __restrict__ b2, const float* __restrict__ logit,
                           float4* __restrict__ out) {
    int gt = blockIdx.x * blockDim.x + threadIdx.x;
    int d = gt >> 5, lane = gt & 31;
    if (d >= N_NODES) return;
    int s0 = g_rowstart[d], s1 = g_rowstart[d + 1];
    const float4* z4 = (const float4*)g_z;
    float4 acc = z4[(size_t)d * 32 + lane];
    for (int i = s0; i < s1; i += 32) {
        int lim = s1 - i;
#pragma unroll
        for (int j = 0; j < 32; j++) {
            if (j < lim) {
                int s = __ldg(&g_csr[i + j]);
                float4 v = z4[(size_t)s * 32 + lane];
                acc.x += v.x; acc.y += v.y; acc.z += v.z; acc.w += v.w;
            }
        }
    }
    float invd = 1.0f / (float)(s1 - s0 + 1);
    float4 bb = __ldg(&b2[lane]);
    acc.x = acc.x * invd + bb.x;
    acc.y = acc.y * invd + bb.y;
    acc.z = acc.z * invd + bb.z;
    acc.w = acc.w * invd + bb.w;
    float ss = acc.x * acc.x + acc.y * acc.y + acc.z * acc.z + acc.w * acc.w;
#pragma unroll
    for (int off = 16; off > 0; off >>= 1)
        ss += __shfl_xor_sync(0xffffffffu, ss, off);
    float sca = expf(__ldg(logit)) / fmaxf(sqrtf(ss), 1e-12f);
    acc.x *= sca; acc.y *= sca; acc.z *= sca; acc.w *= sca;
    out[(size_t)d * 32 + lane] = acc;
}

// ---------------- launch ----------------
extern "C" void kernel_launch(void* const* d_in, const int* in_sizes, int n_in,
                              void* d_out, int out_size) {
    const void *px = 0, *pei = 0, *pW1 = 0, *pb1 = 0, *pW2 = 0, *pb2 = 0, *pls = 0;
    int nW = 0;
    for (int i = 0; i < n_in; i++) {
        switch (in_sizes[i]) {
            case 6400000: px = d_in[i]; break;
            case 1280000: pei = d_in[i]; break;
            case 32768:   if (nW++ == 0) pW1 = d_in[i]; else pW2 = d_in[i]; break;
            case 256:     pb1 = d_in[i]; break;
            case 128:     pb2 = d_in[i]; break;
            case 1:       pls = d_in[i]; break;
            default: break;
        }
    }
    if (!px)  px  = d_in[0];
    if (!pei) pei = d_in[1];
    if (!pW1) pW1 = d_in[2];
    if (!pb1) pb1 = d_in[3];
    if (!pW2) pW2 = d_in[4];
    if (!pb2) pb2 = d_in[5];
    if (!pls) pls = d_in[6];

    const float4* x  = (const float4*)px;
    const int*    ei = (const int*)pei;
    const float*  W1 = (const float*)pW1;
    const float*  b1 = (const float*)pb1;
    const float*  W2 = (const float*)pW2;
    const float4* b2 = (const float4*)pb2;
    const float*  ls = (const float*)pls;
    float4*       out = (float4*)d_out;

    cudaFuncSetAttribute(k_lin1_mma, cudaFuncAttributeMaxDynamicSharedMemorySize, L1_SMEM);
    cudaFuncSetAttribute(k_lin2_mma, cudaFuncAttributeMaxDynamicSharedMemorySize, L2_SMEM);

    int eblocks = (N_EDGES + 255) / 256;
    int nblocks = (N_NODES + 255) / 256;
    int gblocks = (N_NODES * 32 + 255) / 256;   // warp per node

    k_setup<<<nblocks, 256>>>(ei);
    k_deg<<<eblocks, 256>>>(ei);
    k_scan<<<1, 1024>>>();
    k_fill<<<eblocks, 256>>>(ei);
    k_gather1<<<gblocks, 256>>>(x);
    k_lin1_mma<<<148, 256, L1_SMEM>>>(W1, b1);
    k_lin2_mma<<<148, 256, L2_SMEM>>>(W2);
    k_gather2f<<<gblocks, 256>>>(b2, ls, out);
}

// round 11
// speedup vs baseline: 4.7117x; 1.3249x over previous
#include <cuda_runtime.h>
#include <cuda_bf16.h>
#include <mma.h>
#include <math.h>
#include <cstdint>

using namespace nvcuda;

#define N_NODES 50000
#define N_EDGES 640000
#define N_PAD   50048   // 391 tiles * 128 rows
// dims: 128 -> 256 -> 128

// ---------------- scratch (device-code-only references; never host args) ----------------
__device__ float4   g_agg1[N_NODES * 32];    // mean-aggregated x (incl self), f32
__device__ unsigned g_y1h[N_NODES * 128];    // relu(lin1) bf16 hi plane, packed bf16x2
__device__ unsigned g_y1l[N_NODES * 128];    // residual lo plane
__device__ float    g_z  [N_PAD * 128];      // y1 @ W2^T (pre-agg), f32, padded rows
__device__ int      g_dege[N_NODES];
__device__ int      g_rowstart[N_NODES];     // unordered CSR segment starts
__device__ int      g_cursor[N_NODES];
__device__ int      g_csr[N_EDGES];
__device__ int      g_total;                 // CSR allocation counter
__device__ int      g_idx64;

// bf16 hi/lo split of two floats, packed bf16x2 (x -> low half)
union U32B2 { unsigned u; __nv_bfloat162 b; };
__device__ __forceinline__ void split2(float f0, float f1, unsigned& hi, unsigned& lo) {
    U32B2 h, l;
    h.b = __floats2bfloat162_rn(f0, f1);
    l.b = __floats2bfloat162_rn(f0 - __bfloat162float(h.b.x), f1 - __bfloat162float(h.b.y));
    hi = h.u; lo = l.u;
}

// ---------------- edge index accessor (int32 or int64 storage) ----------------
__device__ __forceinline__ int edge_at(const int* __restrict__ ei, int which, int e) {
    if (g_idx64) return ei[((size_t)which * N_EDGES + (size_t)e) * 2];
    return ei[which * N_EDGES + e];
}

__global__ void k_setup(const int* __restrict__ ei) {
    int i = blockIdx.x * blockDim.x + threadIdx.x;
    if (i < N_NODES) g_dege[i] = 0;
    if (i == 0) {
        g_total = 0;
        int orr = 0;
#pragma unroll
        for (int j = 0; j < 16; j++) orr |= ei[2 * j + 1];
        g_idx64 = (orr == 0) ? 1 : 0;
    }
}

__global__ void k_deg(const int* __restrict__ ei) {
    int e = blockIdx.x * blockDim.x + threadIdx.x;
    if (e < N_EDGES) atomicAdd(&g_dege[edge_at(ei, 1, e)], 1);
}

// ---------------- CSR allocation: warp-aggregated atomic (order-free segments) -----------
__global__ void k_alloc() {
    int i = blockIdx.x * blockDim.x + threadIdx.x;
    int lane = threadIdx.x & 31;
    int deg = (i < N_NODES) ? g_dege[i] : 0;
    int x = deg;
#pragma unroll
    for (int off = 1; off < 32; off <<= 1) {
        int y = __shfl_up_sync(0xffffffffu, x, off);
        if (lane >= off) x += y;
    }
    int wtotal = __shfl_sync(0xffffffffu, x, 31);
    int base = 0;
    if (lane == 31) base = atomicAdd(&g_total, wtotal);
    base = __shfl_sync(0xffffffffu, base, 31);
    if (i < N_NODES) {
        int rs = base + x - deg;
        g_rowstart[i] = rs;
        g_cursor[i] = rs;
    }
}

__global__ void k_fill(const int* __restrict__ ei) {
    int e = blockIdx.x * blockDim.x + threadIdx.x;
    if (e >= N_EDGES) return;
    int s = edge_at(ei, 0, e);
    int d = edge_at(ei, 1, e);
    int off = atomicAdd(&g_cursor[d], 1);
    g_csr[off] = s;
}

// ---------------- gather1: agg1[d] = mean(x[d] + sum_{s in N(d)} x[s]) ----------------
__global__ void k_gather1(const float4* __restrict__ x) {
    int gt = blockIdx.x * blockDim.x + threadIdx.x;
    int d = gt >> 5, lane = gt & 31;
    if (d >= N_NODES) return;
    int s0 = g_rowstart[d];
    int s1 = s0 + g_dege[d];
    float4 acc = __ldg(&x[(size_t)d * 32 + lane]);
    for (int i = s0; i < s1; i += 32) {
        int lim = s1 - i;
#pragma unroll
        for (int j = 0; j < 32; j++) {
            if (j < lim) {
                int s = __ldg(&g_csr[i + j]);
                float4 v = __ldg(&x[(size_t)s * 32 + lane]);
                acc.x += v.x; acc.y += v.y; acc.z += v.z; acc.w += v.w;
            }
        }
    }
    float invd = 1.0f / (float)(s1 - s0 + 1);
    acc.x *= invd; acc.y *= invd; acc.z *= invd; acc.w *= invd;
    g_agg1[(size_t)d * 32 + lane] = acc;
}

// ================= lin1: y1 = relu(agg1 @ W1^T + b1), 128->256, WMMA bf16 3-split =======
// 512 threads (16 warps): mg = wid&3 (rows 32*mg..+31), cg = wid>>2 (cols 64*cg..+63).
// smem: W1 hi/lo [256][136] bf16 persistent; A hi/lo [128][136] bf16 per tile;
// A region reused as f32 staging [128][68] for epilogue (one 64-col quarter at a time).
#define L1_LD 136
#define L1_SLD 68
#define L1_WHI 0
#define L1_WLO (256 * L1_LD * 2)
#define L1_A   (2 * 256 * L1_LD * 2)
#define L1_AHI L1_A
#define L1_ALO (L1_A + 128 * L1_LD * 2)
#define L1_SMEM (L1_A + 2 * 128 * L1_LD * 2)    // 208896 bytes
#define L1_TILES ((N_NODES + 127) / 128)        // 391
__global__ void __launch_bounds__(512, 1)
k_lin1_mma(const float* __restrict__ W1, const float* __restrict__ b1) {
    extern __shared__ char smem[];
    __nv_bfloat16* Whi = (__nv_bfloat16*)(smem + L1_WHI);
    __nv_bfloat16* Wlo = (__nv_bfloat16*)(smem + L1_WLO);
    __nv_bfloat16* Ahi = (__nv_bfloat16*)(smem + L1_AHI);
    __nv_bfloat16* Alo = (__nv_bfloat16*)(smem + L1_ALO);
    float* stage = (float*)(smem + L1_A);       // [128][68] f32, overlays A planes
    int t = threadIdx.x, wid = t >> 5;
    int mg = wid & 3, cg = wid >> 2;

    // W1 [256][128] f32 -> bf16 hi/lo planes
    for (int i = t; i < 256 * 128; i += 512) {
        int n = i >> 7, k = i & 127;
        float w = __ldg(&W1[i]);
        __nv_bfloat16 hb = __float2bfloat16(w);
        Whi[n * L1_LD + k] = hb;
        Wlo[n * L1_LD + k] = __float2bfloat16(w - __bfloat162float(hb));
    }
    __syncthreads();

    for (int tile = blockIdx.x; tile < L1_TILES; tile += gridDim.x) {
        int base = tile * 128;
        // load + split A tile
        for (int i = t; i < 128 * 32; i += 512) {
            int r = i >> 5, k4 = i & 31;
            int row = base + r;
            float4 v = make_float4(0.f, 0.f, 0.f, 0.f);
            if (row < N_NODES) v = g_agg1[(size_t)row * 32 + k4];
            uint2 hp, lp;
            split2(v.x, v.y, hp.x, lp.x);
            split2(v.z, v.w, hp.y, lp.y);
            *(uint2*)(Ahi + r * L1_LD + 4 * k4) = hp;
            *(uint2*)(Alo + r * L1_LD + 4 * k4) = lp;
        }
        __syncthreads();

        wmma::fragment<wmma::accumulator, 16, 16, 16, float> acc[2][4];
#pragma unroll
        for (int m = 0; m < 2; m++)
#pragma unroll
            for (int n = 0; n < 4; n++) wmma::fill_fragment(acc[m][n], 0.f);

        int rows0 = mg * 32, cols0 = cg * 64;
#pragma unroll
        for (int ks = 0; ks < 8; ks++) {
            wmma::fragment<wmma::matrix_a, 16, 16, 16, __nv_bfloat16, wmma::row_major> ah[2], al[2];
#pragma unroll
            for (int m = 0; m < 2; m++) {
                wmma::load_matrix_sync(ah[m], Ahi + (rows0 + 16 * m) * L1_LD + ks * 16, L1_LD);
                wmma::load_matrix_sync(al[m], Alo + (rows0 + 16 * m) * L1_LD + ks * 16, L1_LD);
            }
#pragma unroll
            for (int n = 0; n < 4; n++) {
                wmma::fragment<wmma::matrix_b, 16, 16, 16, __nv_bfloat16, wmma::col_major> bh, bl;
                int col = cols0 + 16 * n;
                wmma::load_matrix_sync(bh, Whi + col * L1_LD + ks * 16, L1_LD);
                wmma::load_matrix_sync(bl, Wlo + col * L1_LD + ks * 16, L1_LD);
#pragma unroll
                for (int m = 0; m < 2; m++) {
                    wmma::mma_sync(acc[m][n], ah[m], bh, acc[m][n]);
                    wmma::mma_sync(acc[m][n], ah[m], bl, acc[m][n]);
                    wmma::mma_sync(acc[m][n], al[m], bh, acc[m][n]);
                }
            }
        }

        // epilogue: four 64-col quarters through f32 staging (overlays A region)
#pragma unroll
        for (int h = 0; h < 4; h++) {
            __syncthreads();    // k-loop / previous quarter readers done
            if (cg == h) {
#pragma unroll
                for (int m = 0; m < 2; m++)
#pragma unroll
                    for (int n = 0; n < 4; n++)
                        wmma::store_matrix_sync(stage + (rows0 + 16 * m) * L1_SLD + 16 * n,
                                                acc[m][n], L1_SLD, wmma::mem_row_major);
            }
            __syncthreads();
            for (int i = t; i < 128 * 32; i += 512) {   // pairs of adjacent cols
                int r = i >> 5, p = i & 31, c = 2 * p;
                int row = base + r;
                if (row < N_NODES) {
                    float f0 = fmaxf(stage[r * L1_SLD + c]     + __ldg(&b1[64 * h + c]),     0.f);
                    float f1 = fmaxf(stage[r * L1_SLD + c + 1] + __ldg(&b1[64 * h + c + 1]), 0.f);
                    unsigned hp, lp;
                    split2(f0, f1, hp, lp);
                    g_y1h[(size_t)row * 128 + 32 * h + p] = hp;
                    g_y1l[(size_t)row * 128 + 32 * h + p] = lp;
                }
            }
        }
        __syncthreads();    // staging consumed before next tile's A-load
    }
}

// ================= lin2a: z = y1 @ W2^T, 256->128, WMMA bf16 3-split ====================
// 512 threads (16 warps): mg = wid&3 (rows 32*mg..+31), cg = wid>>2 (cols 32*cg..+31).
// W2 hi/lo planes [128][264] bf16 persistent; A chunked over K (2 x 128).
// Epilogue stores straight to padded g_z (bias folded into gather2f).
#define L2_LD 136
#define L2_WLD 264
#define L2_WHI 0
#define L2_WLO (128 * L2_WLD * 2)
#define L2_A   (2 * 128 * L2_WLD * 2)
#define L2_AHI L2_A
#define L2_ALO (L2_A + 128 * L2_LD * 2)
#define L2_SMEM (L2_A + 2 * 128 * L2_LD * 2)    // 204800 bytes
#define L2_TILES ((N_NODES + 127) / 128)        // 391
__global__ void __launch_bounds__(512, 1)
k_lin2_mma(const float* __restrict__ W2) {
    extern __shared__ char smem[];
    __nv_bfloat16* Whi = (__nv_bfloat16*)(smem + L2_WHI);
    __nv_bfloat16* Wlo = (__nv_bfloat16*)(smem + L2_WLO);
    __nv_bfloat16* Ahi = (__nv_bfloat16*)(smem + L2_AHI);
    __nv_bfloat16* Alo = (__nv_bfloat16*)(smem + L2_ALO);
    int t = threadIdx.x, wid = t >> 5;
    int mg = wid & 3, cg = wid >> 2;

    // W2 [128][256] f32 -> bf16 hi/lo planes
    for (int i = t; i < 128 * 256; i += 512) {
        int n = i >> 8, k = i & 255;
        float w = __ldg(&W2[i]);
        __nv_bfloat16 hb = __float2bfloat16(w);
        Whi[n * L2_WLD + k] = hb;
        Wlo[n * L2_WLD + k] = __float2bfloat16(w - __bfloat162float(hb));
    }
    __syncthreads();

    for (int tile = blockIdx.x; tile < L2_TILES; tile += gridDim.x) {
        int base = tile * 128;
        wmma::fragment<wmma::accumulator, 16, 16, 16, float> acc[2][2];
#pragma unroll
        for (int m = 0; m < 2; m++)
#pragma unroll
            for (int n = 0; n < 2; n++) wmma::fill_fragment(acc[m][n], 0.f);

        int rows0 = mg * 32, cols0 = cg * 32;
        for (int kc = 0; kc < 2; kc++) {
            __syncthreads();    // previous chunk readers done
            for (int i = t; i < 128 * 64; i += 512) {   // u32 = bf16x2 pair
                int r = i >> 6, q = i & 63;
                int row = base + r;
                unsigned hp = 0u, lp = 0u;
                if (row < N_NODES) {
                    hp = g_y1h[(size_t)row * 128 + 64 * kc + q];
                    lp = g_y1l[(size_t)row * 128 + 64 * kc + q];
                }
                *(unsigned*)(Ahi + r * L2_LD + 2 * q) = hp;
                *(unsigned*)(Alo + r * L2_LD + 2 * q) = lp;
            }
            __syncthreads();

#pragma unroll
            for (int ks = 0; ks < 8; ks++) {
                wmma::fragment<wmma::matrix_a, 16, 16, 16, __nv_bfloat16, wmma::row_major> ah[2], al[2];
#pragma unroll
                for (int m = 0; m < 2; m++) {
                    wmma::load_matrix_sync(ah[m], Ahi + (rows0 + 16 * m) * L2_LD + ks * 16, L2_LD);
                    wmma::load_matrix_sync(al[m], Alo + (rows0 + 16 * m) * L2_LD + ks * 16, L2_LD);
                }
                int kglob = 128 * kc + 16 * ks;
#pragma unroll
                for (int n = 0; n < 2; n++) {
                    wmma::fragment<wmma::matrix_b, 16, 16, 16, __nv_bfloat16, wmma::col_major> bh, bl;
                    int col = cols0 + 16 * n;
                    wmma::load_matrix_sync(bh, Whi + col * L2_WLD + kglob, L2_WLD);
                    wmma::load_matrix_sync(bl, Wlo + col * L2_WLD + kglob, L2_WLD);
#pragma unroll
                    for (int m = 0; m < 2; m++) {
                        wmma::mma_sync(acc[m][n], ah[m], bh, acc[m][n]);
                        wmma::mma_sync(acc[m][n], ah[m], bl, acc[m][n]);
                        wmma::mma_sync(acc[m][n], al[m], bh, acc[m][n]);
                    }
                }
            }
        }

        // epilogue: straight to padded g_z (rows >= N_NODES land in pad, never read)
#pragma unroll
        for (int m = 0; m < 2; m++)
#pragma unroll
            for (int n = 0; n < 2; n++)
                wmma::store_matrix_sync(g_z + (size_t)(base + rows0 + 16 * m) * 128 + cols0 + 16 * n,
                                        acc[m][n], 128, wmma::mem_row_major);
    }
}

// ---------------- gather2 + final: out = normalize(mean(z) + b2) * exp(ls) ----------------
__global__ void k_gather2f(const float4* __restrict__ b2, const float* __restrict__ logit,
                           float4* __restrict__ out) {
    int gt = blockIdx.x * blockDim.x + threadIdx.x;
    int d = gt >> 5, lane = gt & 31;
    if (d >= N_NODES) return;
    int s0 = g_rowstart[d];
    int s1 = s0 + g_dege[d];
    const float4* z4 = (const float4*)g_z;
    float4 acc = z4[(size_t)d * 32 + lane];
    for (int i = s0; i < s1; i += 32) {
        int lim = s1 - i;
#pragma unroll
        for (int j = 0; j < 32; j++) {
            if (j < lim) {
                int s = __ldg(&g_csr[i + j]);
                float4 v = z4[(size_t)s * 32 + lane];
                acc.x += v.x; acc.y += v.y; acc.z += v.z; acc.w += v.w;
            }
        }
    }
    float invd = 1.0f / (float)(s1 - s0 + 1);
    float4 bb = __ldg(&b2[lane]);
    acc.x = acc.x * invd + bb.x;
    acc.y = acc.y * invd + bb.y;
    acc.z = acc.z * invd + bb.z;
    acc.w = acc.w * invd + bb.w;
    float ss = acc.x * acc.x + acc.y * acc.y + acc.z * acc.z + acc.w * acc.w;
#pragma unroll
    for (int off = 16; off > 0; off >>= 1)
        ss += __shfl_xor_sync(0xffffffffu, ss, off);
    float sca = expf(__ldg(logit)) / fmaxf(sqrtf(ss), 1e-12f);
    acc.x *= sca; acc.y *= sca; acc.z *= sca; acc.w *= sca;
    out[(size_t)d * 32 + lane] = acc;
}

// ---------------- launch ----------------
extern "C" void kernel_launch(void* const* d_in, const int* in_sizes, int n_in,
                              void* d_out, int out_size) {
    const void *px = 0, *pei = 0, *pW1 = 0, *pb1 = 0, *pW2 = 0, *pb2 = 0, *pls = 0;
    int nW = 0;
    for (int i = 0; i < n_in; i++) {
        switch (in_sizes[i]) {
            case 6400000: px = d_in[i]; break;
            case 1280000: pei = d_in[i]; break;
            case 32768:   if (nW++ == 0) pW1 = d_in[i]; else pW2 = d_in[i]; break;
            case 256:     pb1 = d_in[i]; break;
            case 128:     pb2 = d_in[i]; break;
            case 1:       pls = d_in[i]; break;
            default: break;
        }
    }
    if (!px)  px  = d_in[0];
    if (!pei) pei = d_in[1];
    if (!pW1) pW1 = d_in[2];
    if (!pb1) pb1 = d_in[3];
    if (!pW2) pW2 = d_in[4];
    if (!pb2) pb2 = d_in[5];
    if (!pls) pls = d_in[6];

    const float4* x  = (const float4*)px;
    const int*    ei = (const int*)pei;
    const float*  W1 = (const float*)pW1;
    const float*  b1 = (const float*)pb1;
    const float*  W2 = (const float*)pW2;
    const float4* b2 = (const float4*)pb2;
    const float*  ls = (const float*)pls;
    float4*       out = (float4*)d_out;

    cudaFuncSetAttribute(k_lin1_mma, cudaFuncAttributeMaxDynamicSharedMemorySize, L1_SMEM);
    cudaFuncSetAttribute(k_lin2_mma, cudaFuncAttributeMaxDynamicSharedMemorySize, L2_SMEM);

    int eblocks = (N_EDGES + 255) / 256;
    int nblocks = (N_NODES + 255) / 256;
    int gblocks = (N_NODES * 32 + 255) / 256;   // warp per node

    k_setup<<<nblocks, 256>>>(ei);
    k_deg<<<eblocks, 256>>>(ei);
    k_alloc<<<nblocks, 256>>>();
    k_fill<<<eblocks, 256>>>(ei);
    k_gather1<<<gblocks, 256>>>(x);
    k_lin1_mma<<<148, 512, L1_SMEM>>>(W1, b1);
    k_lin2_mma<<<148, 512, L2_SMEM>>>(W2);
    k_gather2f<<<gblocks, 256>>>(b2, ls, out);
}